// round 5
// baseline (speedup 1.0000x reference)
#include <cuda_runtime.h>

// Problem constants (fixed by the dataset; arrays sized to them)
#define MAXN 100000
#define MAXE 1200000
#define DIM  64
#define MAXG 128
#define SCAN_B 1024   // elements per scan block

// ---------------- scratch (static device globals; no allocation) -------------
__device__ int   g_indeg[MAXN];
__device__ int   g_fill[MAXN];        // CSR cursor (init = rowptr)
__device__ int   g_rowptr[MAXN + 1];
__device__ float g_dinv[MAXN];
__device__ int   g_col[MAXE];
__device__ float g_tmp[(size_t)MAXN * DIM];   // gemm out (u) / agg out (h)
__device__ float g_h[(size_t)MAXN * DIM];     // prescaled features (u*dinv)
__device__ float g_pooled[MAXG * DIM];
__device__ int   g_counts[MAXG];
__device__ int   g_bsum[1024];        // per-block degree sums
__device__ int   g_idx64;             // 1 if indices are int64, 0 if int32

// Flag-dispatched index load (int32[] or int64[]; values < 2^31).
__device__ __forceinline__ int load_idx(const void* p, long long i) {
    if (g_idx64) return (int)((const long long*)p)[i];
    return ((const int*)p)[i];
}

// ---------------- packed f32x2 helpers (Blackwell) ---------------------------
__device__ __forceinline__ unsigned long long pack2(float x, float y) {
    unsigned long long r;
    asm("mov.b64 %0,{%1,%2};" : "=l"(r) : "f"(x), "f"(y));
    return r;
}
__device__ __forceinline__ void fma2(unsigned long long& d,
                                     unsigned long long a,
                                     unsigned long long b) {
    asm("fma.rn.f32x2 %0,%1,%2,%0;" : "+l"(d) : "l"(a), "l"(b));
}
__device__ __forceinline__ void fadd2(unsigned long long& d,
                                      unsigned long long a) {
    asm("add.rn.f32x2 %0,%0,%1;" : "+l"(d) : "l"(a));
}
union F4U { float4 f4; unsigned long long u[2]; float f[4]; };

// ---------------- detect dtype + zero scratch (one kernel) -------------------
__global__ void detect_zero_kernel(const int* __restrict__ ei32, int n, int g) {
    if (blockIdx.x == 0 && threadIdx.x == 0) {
        // int64 edge_index => every odd int32 word (high half) of the first
        // 32 values is 0. int32 => odd words are random node ids.
        int all_zero = 1;
        for (int k = 0; k < 32; k++)
            if (ei32[2 * k + 1] != 0) all_zero = 0;
        g_idx64 = all_zero;
    }
    int stride = gridDim.x * blockDim.x;
    int t = blockIdx.x * blockDim.x + threadIdx.x;
    for (int i = t; i < n; i += stride) g_indeg[i] = 0;
    for (int i = t; i < g * DIM; i += stride) g_pooled[i] = 0.0f;
    for (int i = t; i < g; i += stride) g_counts[i] = 0;
}

// ---------------- degree histogram (at destination) --------------------------
__global__ void degree_kernel(const void* __restrict__ ei, int e) {
    int stride = gridDim.x * blockDim.x;
    for (int i = blockIdx.x * blockDim.x + threadIdx.x; i < e; i += stride)
        atomicAdd(&g_indeg[load_idx(ei, (long long)e + i)], 1);
}

// ---------------- scan phase 1: per-block degree sums ------------------------
__global__ void scan1_kernel(int n) {
    __shared__ int wsum[32];
    int b = blockIdx.x, t = threadIdx.x;
    int i = b * SCAN_B + t;
    int lane = t & 31, wi = t >> 5;
    int v = (i < n) ? g_indeg[i] : 0;
#pragma unroll
    for (int off = 16; off > 0; off >>= 1)
        v += __shfl_down_sync(0xffffffffu, v, off);
    if (lane == 0) wsum[wi] = v;
    __syncthreads();
    if (wi == 0) {
        int s = wsum[lane];
#pragma unroll
        for (int off = 16; off > 0; off >>= 1)
            s += __shfl_down_sync(0xffffffffu, s, off);
        if (lane == 0) g_bsum[b] = s;
    }
}

// ---------------- scan phase 2+3: rowptr + fill + dinv + prescale + counts ---
// Also prescales g_tmp (=x@W0) by dinv into g_h, and accumulates graph counts.
__global__ void scan23_kernel(const void* __restrict__ batch, int n) {
    __shared__ int s_boff;
    __shared__ int wtot[32];
    int b = blockIdx.x, t = threadIdx.x;
    int lane = t & 31, wi = t >> 5;
    int i = b * SCAN_B + t;

    // block offset: warp 0 sums bsum[0..b-1] (<= 97 values)
    if (wi == 0) {
        int sum = 0;
        for (int j = lane; j < b; j += 32) sum += g_bsum[j];
#pragma unroll
        for (int off = 16; off > 0; off >>= 1)
            sum += __shfl_down_sync(0xffffffffu, sum, off);
        if (lane == 0) s_boff = sum;
    }

    int v = (i < n) ? g_indeg[i] : 0;
    int x = v;
#pragma unroll
    for (int off = 1; off < 32; off <<= 1) {     // inclusive warp scan
        int y = __shfl_up_sync(0xffffffffu, x, off);
        if (lane >= off) x += y;
    }
    if (lane == 31) wtot[wi] = x;
    __syncthreads();
    if (wi == 0) {
        int y = wtot[lane];
        int z = y;
#pragma unroll
        for (int off = 1; off < 32; off <<= 1) {
            int u = __shfl_up_sync(0xffffffffu, z, off);
            if (lane >= off) z += u;
        }
        wtot[lane] = z - y;                      // exclusive warp offsets
    }
    __syncthreads();

    if (i < n) {
        int excl = x - v + wtot[wi] + s_boff;
        g_rowptr[i] = excl;
        g_fill[i]   = excl;                      // cursor starts at rowptr
        float di = rsqrtf((float)v + 1.0f);
        g_dinv[i] = di;
        if (i == n - 1) g_rowptr[n] = excl + v;
        // prescale layer-1 gemm output: g_h = g_tmp * dinv (row-wise)
        const float4* src4 = (const float4*)&g_tmp[(size_t)i * DIM];
        float4* dst4 = (float4*)&g_h[(size_t)i * DIM];
#pragma unroll
        for (int c = 0; c < 16; c++) {
            float4 u = src4[c];
            u.x *= di; u.y *= di; u.z *= di; u.w *= di;
            dst4[c] = u;
        }
        // graph counts (batch sorted -> warp-uniform -> REDUX aggregated)
        atomicAdd(&g_counts[load_idx(batch, i)], 1);
    }
}

// ---------------- CSR fill: col (src) only -----------------------------------
__global__ void fill_kernel(const void* __restrict__ ei, int e) {
    int stride = gridDim.x * blockDim.x;
    for (int i = blockIdx.x * blockDim.x + threadIdx.x; i < e; i += stride) {
        int s = load_idx(ei, i);                 // src row
        int d = load_idx(ei, (long long)e + i);  // dst row
        int pos = atomicAdd(&g_fill[d], 1);
        g_col[pos] = s;
    }
}

// ---------------- dense GEMM: out[n,64] = in[n,64] @ W[64,64] ----------------
// mode 0: in = x param,  out = g_tmp, no scale   (layer-1, before dinv ready)
// mode 1: in = g_tmp,    out = g_h,   row-scaled by dinv (prescale for agg)
__global__ __launch_bounds__(256) void gemm64_kernel(
    const float* __restrict__ in, const float* __restrict__ W, int n, int mode) {
    __shared__ float sX[64][68];
    __shared__ float sW[64][68];
    const float* src = (mode == 0) ? in : g_tmp;
    float* dst = (mode == 0) ? g_tmp : g_h;
    int t = threadIdx.x;
    int block0 = blockIdx.x * 64;

    for (int i = t; i < 64 * 16; i += 256) {
        int r = i >> 4;
        int c4 = (i & 15) << 2;
        *(float4*)&sW[r][c4] = *(const float4*)&W[r * 64 + c4];
        int node = block0 + r;
        float4 x4 = make_float4(0.f, 0.f, 0.f, 0.f);
        if (node < n)
            x4 = *(const float4*)&src[(size_t)node * 64 + c4];
        *(float4*)&sX[r][c4] = x4;
    }
    __syncthreads();

    int tc = (t & 15) << 2;   // output col base
    int tr = (t >> 4) << 2;   // node base within tile
    unsigned long long acc[4][2] = {};
#pragma unroll
    for (int k = 0; k < 64; k++) {
        const unsigned long long* bp = (const unsigned long long*)&sW[k][tc];
        unsigned long long b01 = bp[0];
        unsigned long long b23 = bp[1];
#pragma unroll
        for (int i = 0; i < 4; i++) {
            float a = sX[tr + i][k];
            unsigned long long aa = pack2(a, a);
            fma2(acc[i][0], aa, b01);
            fma2(acc[i][1], aa, b23);
        }
    }
#pragma unroll
    for (int i = 0; i < 4; i++) {
        int node = block0 + tr + i;
        if (node < n) {
            float sc = mode ? g_dinv[node] : 1.0f;
            F4U u;
            u.u[0] = acc[i][0];
            u.u[1] = acc[i][1];
            u.f4.x *= sc; u.f4.y *= sc; u.f4.z *= sc; u.f4.w *= sc;
            *(float4*)&dst[(size_t)node * 64 + tc] = u.f4;
        }
    }
}

// ---------------- aggregation: warp/node, half-warp/edge, packed adds --------
// g_tmp[i] = relu( dinv[i] * ( sum_e g_h[col[e]] + g_h[i] ) + b )
__global__ __launch_bounds__(256) void aggregate_kernel(
    const float* __restrict__ b, int n) {
    int warp = (blockIdx.x * blockDim.x + threadIdx.x) >> 5;
    if (warp >= n) return;
    int lane = threadIdx.x & 31;
    int half = lane >> 4;     // which edge of the pair
    int q = lane & 15;        // feature group (float4)
    int s = g_rowptr[warp];
    int e = g_rowptr[warp + 1];
    float di = g_dinv[warp];

    unsigned long long acc0 = 0, acc1 = 0;
    if (half == 0) {          // self term once
        F4U u;
        u.f4 = *(const float4*)&g_h[(size_t)warp * 64 + q * 4];
        acc0 = u.u[0];
        acc1 = u.u[1];
    }

    // depth-2 prefetch: two gathers in flight per half-warp
    int p = s + half;
    int sA = (p < e) ? g_col[p] : -1;
    int sB = (p + 2 < e) ? g_col[p + 2] : -1;
    F4U vA;
    vA.f4 = make_float4(0.f, 0.f, 0.f, 0.f);
    if (sA >= 0)
        vA.f4 = *(const float4*)&g_h[(size_t)sA * 64 + q * 4];
    while (p < e) {
        int pn = p + 2;
        int sC = (pn + 2 < e) ? g_col[pn + 2] : -1;
        F4U vB;
        vB.f4 = make_float4(0.f, 0.f, 0.f, 0.f);
        if (sB >= 0)
            vB.f4 = *(const float4*)&g_h[(size_t)sB * 64 + q * 4];
        fadd2(acc0, vA.u[0]);
        fadd2(acc1, vA.u[1]);
        vA = vB;
        sB = sC;
        p = pn;
    }

    // combine the two half-warp accumulators (64-bit shfl)
    unsigned long long o0 = __shfl_down_sync(0xffffffffu, acc0, 16);
    unsigned long long o1 = __shfl_down_sync(0xffffffffu, acc1, 16);
    fadd2(acc0, o0);
    fadd2(acc1, o1);

    if (half == 0) {
        F4U u;
        u.u[0] = acc0;
        u.u[1] = acc1;
        float4 bb = *(const float4*)&b[q * 4];
        float4 r;
        r.x = fmaxf(u.f4.x * di + bb.x, 0.f);
        r.y = fmaxf(u.f4.y * di + bb.y, 0.f);
        r.z = fmaxf(u.f4.z * di + bb.z, 0.f);
        r.w = fmaxf(u.f4.w * di + bb.w, 0.f);
        *(float4*)&g_tmp[(size_t)warp * 64 + q * 4] = r;
    }
}

// ---------------- pooling: exploit sorted batch, flush per graph-run ---------
__global__ void pool_kernel(const void* __restrict__ batch, int n) {
    int warp = (blockIdx.x * blockDim.x + threadIdx.x) >> 5;
    int lane = threadIdx.x & 31;
    int base = warp * 64;
    if (base >= n) return;
    int end = min(base + 64, n);
    int cg = load_idx(batch, base);
    float2 acc = make_float2(0.f, 0.f);
    for (int i = base; i < end; i++) {
        int g = load_idx(batch, i);
        if (g != cg) {
            atomicAdd(&g_pooled[cg * 64 + lane * 2 + 0], acc.x);
            atomicAdd(&g_pooled[cg * 64 + lane * 2 + 1], acc.y);
            acc = make_float2(0.f, 0.f);
            cg = g;
        }
        float2 v = *(const float2*)&g_tmp[(size_t)i * 64 + lane * 2];
        acc.x += v.x;
        acc.y += v.y;
    }
    atomicAdd(&g_pooled[cg * 64 + lane * 2 + 0], acc.x);
    atomicAdd(&g_pooled[cg * 64 + lane * 2 + 1], acc.y);
}

// ---------------- final: mean + linear head ----------------------------------
__global__ void final_kernel(const float* __restrict__ lin_w,
                             const float* __restrict__ lin_b,
                             float* __restrict__ out, int g) {
    int i = blockIdx.x * blockDim.x + threadIdx.x;
    if (i >= g) return;
    float cnt = fmaxf((float)g_counts[i], 1.0f);
    float inv = 1.0f / cnt;
    float a0 = lin_b[0];
    float a1 = lin_b[1];
#pragma unroll
    for (int d = 0; d < 64; d++) {
        float p = g_pooled[i * 64 + d] * inv;
        a0 += p * lin_w[d * 2 + 0];
        a1 += p * lin_w[d * 2 + 1];
    }
    out[i * 2 + 0] = a0;
    out[i * 2 + 1] = a1;
}

// ---------------- launch ------------------------------------------------------
extern "C" void kernel_launch(void* const* d_in, const int* in_sizes, int n_in,
                              void* d_out, int out_size) {
    const float* x     = (const float*)d_in[0];
    const void*  ei    = d_in[1];
    const void*  batch = d_in[2];
    const float* W0    = (const float*)d_in[3];
    const float* b0    = (const float*)d_in[4];
    const float* W1    = (const float*)d_in[5];
    const float* b1    = (const float*)d_in[6];
    const float* W2    = (const float*)d_in[7];
    const float* b2    = (const float*)d_in[8];
    const float* lin_w = (const float*)d_in[9];
    const float* lin_b = (const float*)d_in[10];

    int n = in_sizes[0] / DIM;       // 100000
    int e = in_sizes[1] / 2;         // 1200000
    int nc = in_sizes[10];           // 2
    int g = out_size / nc;           // 128

    int nb = (n + SCAN_B - 1) / SCAN_B;   // 98 scan blocks
    int gemm_blocks = (n + 63) / 64;
    long long agg_threads = (long long)n * 32;
    int agg_blocks = (int)((agg_threads + 255) / 256);

    // launch index:                                          profiled = #3
    detect_zero_kernel<<<200, 512>>>((const int*)ei, n, g);        // 0
    degree_kernel<<<(e + 511) / 512, 512>>>(ei, e);                // 1
    scan1_kernel<<<nb, SCAN_B>>>(n);                               // 2
    gemm64_kernel<<<gemm_blocks, 256>>>(x, W0, n, 0);              // 3  <- ncu
    scan23_kernel<<<nb, SCAN_B>>>(batch, n);                       // 4
    fill_kernel<<<(e + 511) / 512, 512>>>(ei, e);                  // 5
    aggregate_kernel<<<agg_blocks, 256>>>(b0, n);                  // 6
    gemm64_kernel<<<gemm_blocks, 256>>>(nullptr, W1, n, 1);        // 7
    aggregate_kernel<<<agg_blocks, 256>>>(b1, n);                  // 8
    gemm64_kernel<<<gemm_blocks, 256>>>(nullptr, W2, n, 1);        // 9
    aggregate_kernel<<<agg_blocks, 256>>>(b2, n);                  // 10
    pool_kernel<<<((n + 63) / 64 * 32 + 255) / 256, 256>>>(batch, n); // 11
    final_kernel<<<1, 128>>>(lin_w, lin_b, (float*)d_out, g);      // 12
}

// round 7
// speedup vs baseline: 1.0619x; 1.0619x over previous
#include <cuda_runtime.h>

// Problem constants (fixed by the dataset; arrays sized to them)
#define MAXN 100000
#define MAXE 1200000
#define DIM  64
#define MAXG 128
#define SCAN_B 1024   // elements per scan block

// ---------------- scratch (static device globals; no allocation) -------------
__device__ int   g_indeg[MAXN];
__device__ int   g_fill[MAXN];        // CSR cursor (init = rowptr)
__device__ int   g_rowptr[MAXN + 1];
__device__ float g_dinv[MAXN];
__device__ int   g_col[MAXE];
__device__ float g_tmp[(size_t)MAXN * DIM];   // agg output (layer features)
__device__ float g_h[(size_t)MAXN * DIM];     // gemm output, prescaled by dinv
__device__ float g_pooled[MAXG * DIM];
__device__ int   g_counts[MAXG];
__device__ int   g_bsum[1024];        // per-block degree sums
__device__ int   g_idx64;             // 1 if indices are int64, 0 if int32

// Flag-dispatched index load (int32[] or int64[]; values < 2^31).
__device__ __forceinline__ int load_idx(const void* p, long long i) {
    if (g_idx64) return (int)((const long long*)p)[i];
    return ((const int*)p)[i];
}

// ---------------- packed f32x2 helpers (Blackwell) ---------------------------
__device__ __forceinline__ unsigned long long pack2(float x, float y) {
    unsigned long long r;
    asm("mov.b64 %0,{%1,%2};" : "=l"(r) : "f"(x), "f"(y));
    return r;
}
__device__ __forceinline__ void fma2(unsigned long long& d,
                                     unsigned long long a,
                                     unsigned long long b) {
    asm("fma.rn.f32x2 %0,%1,%2,%0;" : "+l"(d) : "l"(a), "l"(b));
}
__device__ __forceinline__ void fadd2(unsigned long long& d,
                                      unsigned long long a) {
    asm("add.rn.f32x2 %0,%0,%1;" : "+l"(d) : "l"(a));
}
union F4U { float4 f4; unsigned long long u[2]; float f[4]; };

// ---------------- detect dtype + zero scratch (one kernel) -------------------
__global__ void detect_zero_kernel(const int* __restrict__ ei32, int n, int g) {
    if (blockIdx.x == 0 && threadIdx.x == 0) {
        // int64 edge_index => every odd int32 word (high half) of the first
        // 32 values is 0. int32 => odd words are random node ids.
        int all_zero = 1;
        for (int k = 0; k < 32; k++)
            if (ei32[2 * k + 1] != 0) all_zero = 0;
        g_idx64 = all_zero;
    }
    int stride = gridDim.x * blockDim.x;
    int t = blockIdx.x * blockDim.x + threadIdx.x;
    for (int i = t; i < n; i += stride) g_indeg[i] = 0;
    for (int i = t; i < g * DIM; i += stride) g_pooled[i] = 0.0f;
    for (int i = t; i < g; i += stride) g_counts[i] = 0;
}

// ---------------- degree histogram (at destination) --------------------------
__global__ void degree_kernel(const void* __restrict__ ei, int e) {
    int stride = gridDim.x * blockDim.x;
    for (int i = blockIdx.x * blockDim.x + threadIdx.x; i < e; i += stride)
        atomicAdd(&g_indeg[load_idx(ei, (long long)e + i)], 1);
}

// ---------------- scan phase 1: per-block degree sums ------------------------
__global__ void scan1_kernel(int n) {
    __shared__ int wsum[32];
    int b = blockIdx.x, t = threadIdx.x;
    int i = b * SCAN_B + t;
    int lane = t & 31, wi = t >> 5;
    int v = (i < n) ? g_indeg[i] : 0;
#pragma unroll
    for (int off = 16; off > 0; off >>= 1)
        v += __shfl_down_sync(0xffffffffu, v, off);
    if (lane == 0) wsum[wi] = v;
    __syncthreads();
    if (wi == 0) {
        int s = wsum[lane];
#pragma unroll
        for (int off = 16; off > 0; off >>= 1)
            s += __shfl_down_sync(0xffffffffu, s, off);
        if (lane == 0) g_bsum[b] = s;
    }
}

// ---------------- scan phase 2+3: rowptr + fill cursor + dinv + counts -------
__global__ void scan23_kernel(const void* __restrict__ batch, int n) {
    __shared__ int s_boff;
    __shared__ int wtot[32];
    int b = blockIdx.x, t = threadIdx.x;
    int lane = t & 31, wi = t >> 5;
    int i = b * SCAN_B + t;

    // block offset: warp 0 sums bsum[0..b-1] (<= 97 values)
    if (wi == 0) {
        int sum = 0;
        for (int j = lane; j < b; j += 32) sum += g_bsum[j];
#pragma unroll
        for (int off = 16; off > 0; off >>= 1)
            sum += __shfl_down_sync(0xffffffffu, sum, off);
        if (lane == 0) s_boff = sum;
    }

    int v = (i < n) ? g_indeg[i] : 0;
    int x = v;
#pragma unroll
    for (int off = 1; off < 32; off <<= 1) {     // inclusive warp scan
        int y = __shfl_up_sync(0xffffffffu, x, off);
        if (lane >= off) x += y;
    }
    if (lane == 31) wtot[wi] = x;
    __syncthreads();
    if (wi == 0) {
        int y = wtot[lane];
        int z = y;
#pragma unroll
        for (int off = 1; off < 32; off <<= 1) {
            int u = __shfl_up_sync(0xffffffffu, z, off);
            if (lane >= off) z += u;
        }
        wtot[lane] = z - y;                      // exclusive warp offsets
    }
    __syncthreads();

    if (i < n) {
        int excl = x - v + wtot[wi] + s_boff;
        g_rowptr[i] = excl;
        g_fill[i]   = excl;                      // cursor starts at rowptr
        g_dinv[i]   = rsqrtf((float)v + 1.0f);
        if (i == n - 1) g_rowptr[n] = excl + v;
        // graph counts (batch sorted -> warp-uniform -> aggregated atomics)
        atomicAdd(&g_counts[load_idx(batch, i)], 1);
    }
}

// ---------------- CSR fill: col (src) only -----------------------------------
__global__ void fill_kernel(const void* __restrict__ ei, int e) {
    int stride = gridDim.x * blockDim.x;
    for (int i = blockIdx.x * blockDim.x + threadIdx.x; i < e; i += stride) {
        int s = load_idx(ei, i);                 // src row
        int d = load_idx(ei, (long long)e + i);  // dst row
        int pos = atomicAdd(&g_fill[d], 1);
        g_col[pos] = s;
    }
}

// ---------------- dense GEMM: g_h[n,64] = (in[n,64] @ W[64,64]) * dinv -------
// in == nullptr means "read from g_tmp". Output rows prescaled by dinv for agg.
// LDS-optimized: k-loop in steps of 4, A and B both via LDS.128.
// Per warp per k: 1 wavefront (A, 2-addr broadcast) + 2 (B) = 3 (was 8).
__global__ __launch_bounds__(256) void gemm64_kernel(
    const float* __restrict__ in, const float* __restrict__ W, int n) {
    __shared__ float sX[64][68];
    __shared__ float sW[64][68];
    const float* src = (in == nullptr) ? g_tmp : in;
    int t = threadIdx.x;
    int block0 = blockIdx.x * 64;

    for (int i = t; i < 64 * 16; i += 256) {
        int r = i >> 4;
        int c4 = (i & 15) << 2;
        *(float4*)&sW[r][c4] = *(const float4*)&W[r * 64 + c4];
        int node = block0 + r;
        float4 x4 = make_float4(0.f, 0.f, 0.f, 0.f);
        if (node < n)
            x4 = *(const float4*)&src[(size_t)node * 64 + c4];
        *(float4*)&sX[r][c4] = x4;
    }
    __syncthreads();

    int tc = (t & 15) << 2;   // output col base (16B aligned: stride 272B)
    int tr = (t >> 4) << 2;   // node base within tile
    unsigned long long acc[4][2] = {};
#pragma unroll
    for (int k4 = 0; k4 < 64; k4 += 4) {
        float4 a[4];
#pragma unroll
        for (int i = 0; i < 4; i++)
            a[i] = *(const float4*)&sX[tr + i][k4];   // LDS.128 along k
#pragma unroll
        for (int j = 0; j < 4; j++) {
            const unsigned long long* bp =
                (const unsigned long long*)&sW[k4 + j][tc];
            unsigned long long b01 = bp[0];
            unsigned long long b23 = bp[1];
            float aj0 = (&a[0].x)[j];
            float aj1 = (&a[1].x)[j];
            float aj2 = (&a[2].x)[j];
            float aj3 = (&a[3].x)[j];
            unsigned long long p0 = pack2(aj0, aj0);
            unsigned long long p1 = pack2(aj1, aj1);
            unsigned long long p2 = pack2(aj2, aj2);
            unsigned long long p3 = pack2(aj3, aj3);
            fma2(acc[0][0], p0, b01); fma2(acc[0][1], p0, b23);
            fma2(acc[1][0], p1, b01); fma2(acc[1][1], p1, b23);
            fma2(acc[2][0], p2, b01); fma2(acc[2][1], p2, b23);
            fma2(acc[3][0], p3, b01); fma2(acc[3][1], p3, b23);
        }
    }
#pragma unroll
    for (int i = 0; i < 4; i++) {
        int node = block0 + tr + i;
        if (node < n) {
            float sc = g_dinv[node];
            F4U u;
            u.u[0] = acc[i][0];
            u.u[1] = acc[i][1];
            u.f4.x *= sc; u.f4.y *= sc; u.f4.z *= sc; u.f4.w *= sc;
            *(float4*)&g_h[(size_t)node * 64 + tc] = u.f4;
        }
    }
}

// ---------------- aggregation: warp/node, half-warp/edge, packed adds --------
// g_tmp[i] = relu( dinv[i] * ( sum_e g_h[col[e]] + g_h[i] ) + b )
__global__ __launch_bounds__(256) void aggregate_kernel(
    const float* __restrict__ b, int n) {
    int warp = (blockIdx.x * blockDim.x + threadIdx.x) >> 5;
    if (warp >= n) return;
    int lane = threadIdx.x & 31;
    int half = lane >> 4;     // which edge of the pair
    int q = lane & 15;        // feature group (float4)
    int s = g_rowptr[warp];
    int e = g_rowptr[warp + 1];
    float di = g_dinv[warp];

    unsigned long long acc0 = 0, acc1 = 0;
    if (half == 0) {          // self term once
        F4U u;
        u.f4 = *(const float4*)&g_h[(size_t)warp * 64 + q * 4];
        acc0 = u.u[0];
        acc1 = u.u[1];
    }

    // depth-2 prefetch: two gathers in flight per half-warp
    int p = s + half;
    int sA = (p < e) ? g_col[p] : -1;
    int sB = (p + 2 < e) ? g_col[p + 2] : -1;
    F4U vA;
    vA.f4 = make_float4(0.f, 0.f, 0.f, 0.f);
    if (sA >= 0)
        vA.f4 = *(const float4*)&g_h[(size_t)sA * 64 + q * 4];
    while (p < e) {
        int pn = p + 2;
        int sC = (pn + 2 < e) ? g_col[pn + 2] : -1;
        F4U vB;
        vB.f4 = make_float4(0.f, 0.f, 0.f, 0.f);
        if (sB >= 0)
            vB.f4 = *(const float4*)&g_h[(size_t)sB * 64 + q * 4];
        fadd2(acc0, vA.u[0]);
        fadd2(acc1, vA.u[1]);
        vA = vB;
        sB = sC;
        p = pn;
    }

    // combine the two half-warp accumulators (64-bit shfl)
    unsigned long long o0 = __shfl_down_sync(0xffffffffu, acc0, 16);
    unsigned long long o1 = __shfl_down_sync(0xffffffffu, acc1, 16);
    fadd2(acc0, o0);
    fadd2(acc1, o1);

    if (half == 0) {
        F4U u;
        u.u[0] = acc0;
        u.u[1] = acc1;
        float4 bb = *(const float4*)&b[q * 4];
        float4 r;
        r.x = fmaxf(u.f4.x * di + bb.x, 0.f);
        r.y = fmaxf(u.f4.y * di + bb.y, 0.f);
        r.z = fmaxf(u.f4.z * di + bb.z, 0.f);
        r.w = fmaxf(u.f4.w * di + bb.w, 0.f);
        *(float4*)&g_tmp[(size_t)warp * 64 + q * 4] = r;
    }
}

// ---------------- pooling: exploit sorted batch, flush per graph-run ---------
__global__ void pool_kernel(const void* __restrict__ batch, int n) {
    int warp = (blockIdx.x * blockDim.x + threadIdx.x) >> 5;
    int lane = threadIdx.x & 31;
    int base = warp * 64;
    if (base >= n) return;
    int end = min(base + 64, n);
    int cg = load_idx(batch, base);
    float2 acc = make_float2(0.f, 0.f);
    for (int i = base; i < end; i++) {
        int g = load_idx(batch, i);
        if (g != cg) {
            atomicAdd(&g_pooled[cg * 64 + lane * 2 + 0], acc.x);
            atomicAdd(&g_pooled[cg * 64 + lane * 2 + 1], acc.y);
            acc = make_float2(0.f, 0.f);
            cg = g;
        }
        float2 v = *(const float2*)&g_tmp[(size_t)i * 64 + lane * 2];
        acc.x += v.x;
        acc.y += v.y;
    }
    atomicAdd(&g_pooled[cg * 64 + lane * 2 + 0], acc.x);
    atomicAdd(&g_pooled[cg * 64 + lane * 2 + 1], acc.y);
}

// ---------------- final: mean + linear head ----------------------------------
__global__ void final_kernel(const float* __restrict__ lin_w,
                             const float* __restrict__ lin_b,
                             float* __restrict__ out, int g) {
    int i = blockIdx.x * blockDim.x + threadIdx.x;
    if (i >= g) return;
    float cnt = fmaxf((float)g_counts[i], 1.0f);
    float inv = 1.0f / cnt;
    float a0 = lin_b[0];
    float a1 = lin_b[1];
#pragma unroll
    for (int d = 0; d < 64; d++) {
        float p = g_pooled[i * 64 + d] * inv;
        a0 += p * lin_w[d * 2 + 0];
        a1 += p * lin_w[d * 2 + 1];
    }
    out[i * 2 + 0] = a0;
    out[i * 2 + 1] = a1;
}

// ---------------- launch ------------------------------------------------------
extern "C" void kernel_launch(void* const* d_in, const int* in_sizes, int n_in,
                              void* d_out, int out_size) {
    const float* x     = (const float*)d_in[0];
    const void*  ei    = d_in[1];
    const void*  batch = d_in[2];
    const float* W0    = (const float*)d_in[3];
    const float* b0    = (const float*)d_in[4];
    const float* W1    = (const float*)d_in[5];
    const float* b1    = (const float*)d_in[6];
    const float* W2    = (const float*)d_in[7];
    const float* b2    = (const float*)d_in[8];
    const float* lin_w = (const float*)d_in[9];
    const float* lin_b = (const float*)d_in[10];

    int n = in_sizes[0] / DIM;       // 100000
    int e = in_sizes[1] / 2;         // 1200000
    int nc = in_sizes[10];           // 2
    int g = out_size / nc;           // 128

    int nb = (n + SCAN_B - 1) / SCAN_B;   // 98 scan blocks
    int gemm_blocks = (n + 63) / 64;
    long long agg_threads = (long long)n * 32;
    int agg_blocks = (int)((agg_threads + 255) / 256);

    detect_zero_kernel<<<200, 512>>>((const int*)ei, n, g);        // 0
    degree_kernel<<<(e + 511) / 512, 512>>>(ei, e);                // 1
    scan1_kernel<<<nb, SCAN_B>>>(n);                               // 2
    scan23_kernel<<<nb, SCAN_B>>>(batch, n);                       // 3 <- ncu
    gemm64_kernel<<<gemm_blocks, 256>>>(x, W0, n);                 // 4
    fill_kernel<<<(e + 511) / 512, 512>>>(ei, e);                  // 5
    aggregate_kernel<<<agg_blocks, 256>>>(b0, n);                  // 6
    gemm64_kernel<<<gemm_blocks, 256>>>(nullptr, W1, n);           // 7
    aggregate_kernel<<<agg_blocks, 256>>>(b1, n);                  // 8
    gemm64_kernel<<<gemm_blocks, 256>>>(nullptr, W2, n);           // 9
    aggregate_kernel<<<agg_blocks, 256>>>(b2, n);                  // 10
    pool_kernel<<<((n + 63) / 64 * 32 + 255) / 256, 256>>>(batch, n); // 11
    final_kernel<<<1, 128>>>(lin_w, lin_b, (float*)d_out, g);      // 12
}

// round 8
// speedup vs baseline: 1.1599x; 1.0923x over previous
#include <cuda_runtime.h>

// Problem constants (fixed by the dataset; arrays sized to them)
#define MAXN 100000
#define MAXE 1200000
#define DIM  64
#define MAXG 128
#define SCAN_B 1024   // elements per scan block

// ---------------- scratch (static device globals; no allocation) -------------
__device__ int   g_indeg[MAXN];
__device__ int   g_fill[MAXN];        // CSR cursor (init = rowptr)
__device__ int   g_rowptr[MAXN + 1];
__device__ float g_dinv[MAXN];
__device__ int   g_col[MAXE];
__device__ float g_tmp[(size_t)MAXN * DIM];   // agg output (layer features)
__device__ float g_h[(size_t)MAXN * DIM];     // gemm output, prescaled by dinv
__device__ float g_pooled[MAXG * DIM];
__device__ int   g_bsum[1024];        // per-block degree sums
__device__ int   g_idx64;             // 1 if indices are int64, 0 if int32

// Flag-dispatched index load (int32[] or int64[]; values < 2^31).
__device__ __forceinline__ int load_idx(const void* p, long long i) {
    if (g_idx64) return (int)((const long long*)p)[i];
    return ((const int*)p)[i];
}

// ---------------- packed f32x2 helpers (Blackwell) ---------------------------
__device__ __forceinline__ unsigned long long pack2(float x, float y) {
    unsigned long long r;
    asm("mov.b64 %0,{%1,%2};" : "=l"(r) : "f"(x), "f"(y));
    return r;
}
__device__ __forceinline__ void fma2(unsigned long long& d,
                                     unsigned long long a,
                                     unsigned long long b) {
    asm("fma.rn.f32x2 %0,%1,%2,%0;" : "+l"(d) : "l"(a), "l"(b));
}
__device__ __forceinline__ void fadd2(unsigned long long& d,
                                      unsigned long long a) {
    asm("add.rn.f32x2 %0,%0,%1;" : "+l"(d) : "l"(a));
}
union F4U { float4 f4; unsigned long long u[2]; float f[4]; };

// ---------------- detect dtype + zero scratch (one kernel) -------------------
__global__ void detect_zero_kernel(const int* __restrict__ ei32, int n, int g) {
    if (blockIdx.x == 0 && threadIdx.x == 0) {
        // int64 edge_index => every odd int32 word (high half) of the first
        // 32 values is 0. int32 => odd words are random node ids.
        int all_zero = 1;
        for (int k = 0; k < 32; k++)
            if (ei32[2 * k + 1] != 0) all_zero = 0;
        g_idx64 = all_zero;
    }
    int stride = gridDim.x * blockDim.x;
    int t = blockIdx.x * blockDim.x + threadIdx.x;
    for (int i = t; i < n; i += stride) g_indeg[i] = 0;
    for (int i = t; i < g * DIM; i += stride) g_pooled[i] = 0.0f;
}

// ---------------- degree histogram (at destination) --------------------------
__global__ void degree_kernel(const void* __restrict__ ei, int e) {
    int stride = gridDim.x * blockDim.x;
    for (int i = blockIdx.x * blockDim.x + threadIdx.x; i < e; i += stride)
        atomicAdd(&g_indeg[load_idx(ei, (long long)e + i)], 1);
}

// ---------------- scan phase 1: per-block degree sums ------------------------
__global__ void scan1_kernel(int n) {
    __shared__ int wsum[32];
    int b = blockIdx.x, t = threadIdx.x;
    int i = b * SCAN_B + t;
    int lane = t & 31, wi = t >> 5;
    int v = (i < n) ? g_indeg[i] : 0;
#pragma unroll
    for (int off = 16; off > 0; off >>= 1)
        v += __shfl_down_sync(0xffffffffu, v, off);
    if (lane == 0) wsum[wi] = v;
    __syncthreads();
    if (wi == 0) {
        int s = wsum[lane];
#pragma unroll
        for (int off = 16; off > 0; off >>= 1)
            s += __shfl_down_sync(0xffffffffu, s, off);
        if (lane == 0) g_bsum[b] = s;
    }
}

// ---------------- scan phase 2+3: rowptr + fill cursor + dinv ----------------
__global__ void scan23_kernel(int n) {
    __shared__ int s_boff;
    __shared__ int wtot[32];
    int b = blockIdx.x, t = threadIdx.x;
    int lane = t & 31, wi = t >> 5;
    int i = b * SCAN_B + t;

    // block offset: warp 0 sums bsum[0..b-1] (<= 97 values)
    if (wi == 0) {
        int sum = 0;
        for (int j = lane; j < b; j += 32) sum += g_bsum[j];
#pragma unroll
        for (int off = 16; off > 0; off >>= 1)
            sum += __shfl_down_sync(0xffffffffu, sum, off);
        if (lane == 0) s_boff = sum;
    }

    int v = (i < n) ? g_indeg[i] : 0;
    int x = v;
#pragma unroll
    for (int off = 1; off < 32; off <<= 1) {     // inclusive warp scan
        int y = __shfl_up_sync(0xffffffffu, x, off);
        if (lane >= off) x += y;
    }
    if (lane == 31) wtot[wi] = x;
    __syncthreads();
    if (wi == 0) {
        int y = wtot[lane];
        int z = y;
#pragma unroll
        for (int off = 1; off < 32; off <<= 1) {
            int u = __shfl_up_sync(0xffffffffu, z, off);
            if (lane >= off) z += u;
        }
        wtot[lane] = z - y;                      // exclusive warp offsets
    }
    __syncthreads();

    if (i < n) {
        int excl = x - v + wtot[wi] + s_boff;
        g_rowptr[i] = excl;
        g_fill[i]   = excl;                      // cursor starts at rowptr
        g_dinv[i]   = rsqrtf((float)v + 1.0f);
        if (i == n - 1) g_rowptr[n] = excl + v;
    }
}

// ---------------- CSR fill: col (src) only -----------------------------------
__global__ void fill_kernel(const void* __restrict__ ei, int e) {
    int stride = gridDim.x * blockDim.x;
    for (int i = blockIdx.x * blockDim.x + threadIdx.x; i < e; i += stride) {
        int s = load_idx(ei, i);                 // src row
        int d = load_idx(ei, (long long)e + i);  // dst row
        int pos = atomicAdd(&g_fill[d], 1);
        g_col[pos] = s;
    }
}

// ---------------- dense GEMM: g_h[n,64] = (in[n,64] @ W[64,64]) * dinv -------
// in == nullptr means "read from g_tmp". Output rows prescaled by dinv for agg.
// LDS-optimized: k-loop in steps of 4, A and B both via LDS.128.
__global__ __launch_bounds__(256) void gemm64_kernel(
    const float* __restrict__ in, const float* __restrict__ W, int n) {
    __shared__ float sX[64][68];
    __shared__ float sW[64][68];
    const float* src = (in == nullptr) ? g_tmp : in;
    int t = threadIdx.x;
    int block0 = blockIdx.x * 64;

    for (int i = t; i < 64 * 16; i += 256) {
        int r = i >> 4;
        int c4 = (i & 15) << 2;
        *(float4*)&sW[r][c4] = *(const float4*)&W[r * 64 + c4];
        int node = block0 + r;
        float4 x4 = make_float4(0.f, 0.f, 0.f, 0.f);
        if (node < n)
            x4 = *(const float4*)&src[(size_t)node * 64 + c4];
        *(float4*)&sX[r][c4] = x4;
    }
    __syncthreads();

    int tc = (t & 15) << 2;   // output col base (16B aligned: stride 272B)
    int tr = (t >> 4) << 2;   // node base within tile
    unsigned long long acc[4][2] = {};
#pragma unroll
    for (int k4 = 0; k4 < 64; k4 += 4) {
        float4 a[4];
#pragma unroll
        for (int i = 0; i < 4; i++)
            a[i] = *(const float4*)&sX[tr + i][k4];   // LDS.128 along k
#pragma unroll
        for (int j = 0; j < 4; j++) {
            const unsigned long long* bp =
                (const unsigned long long*)&sW[k4 + j][tc];
            unsigned long long b01 = bp[0];
            unsigned long long b23 = bp[1];
            float aj0 = (&a[0].x)[j];
            float aj1 = (&a[1].x)[j];
            float aj2 = (&a[2].x)[j];
            float aj3 = (&a[3].x)[j];
            unsigned long long p0 = pack2(aj0, aj0);
            unsigned long long p1 = pack2(aj1, aj1);
            unsigned long long p2 = pack2(aj2, aj2);
            unsigned long long p3 = pack2(aj3, aj3);
            fma2(acc[0][0], p0, b01); fma2(acc[0][1], p0, b23);
            fma2(acc[1][0], p1, b01); fma2(acc[1][1], p1, b23);
            fma2(acc[2][0], p2, b01); fma2(acc[2][1], p2, b23);
            fma2(acc[3][0], p3, b01); fma2(acc[3][1], p3, b23);
        }
    }
#pragma unroll
    for (int i = 0; i < 4; i++) {
        int node = block0 + tr + i;
        if (node < n) {
            float sc = g_dinv[node];
            F4U u;
            u.u[0] = acc[i][0];
            u.u[1] = acc[i][1];
            u.f4.x *= sc; u.f4.y *= sc; u.f4.z *= sc; u.f4.w *= sc;
            *(float4*)&g_h[(size_t)node * 64 + tc] = u.f4;
        }
    }
}

// ---------------- aggregation: warp/node, half-warp/edge, packed adds --------
// g_tmp[i] = relu( dinv[i] * ( sum_e g_h[col[e]] + g_h[i] ) + b )
__global__ __launch_bounds__(256) void aggregate_kernel(
    const float* __restrict__ b, int n) {
    int warp = (blockIdx.x * blockDim.x + threadIdx.x) >> 5;
    if (warp >= n) return;
    int lane = threadIdx.x & 31;
    int half = lane >> 4;     // which edge of the pair
    int q = lane & 15;        // feature group (float4)
    int s = g_rowptr[warp];
    int e = g_rowptr[warp + 1];
    float di = g_dinv[warp];

    unsigned long long acc0 = 0, acc1 = 0;
    if (half == 0) {          // self term once
        F4U u;
        u.f4 = *(const float4*)&g_h[(size_t)warp * 64 + q * 4];
        acc0 = u.u[0];
        acc1 = u.u[1];
    }

    // depth-2 prefetch: two gathers in flight per half-warp
    int p = s + half;
    int sA = (p < e) ? g_col[p] : -1;
    int sB = (p + 2 < e) ? g_col[p + 2] : -1;
    F4U vA;
    vA.f4 = make_float4(0.f, 0.f, 0.f, 0.f);
    if (sA >= 0)
        vA.f4 = *(const float4*)&g_h[(size_t)sA * 64 + q * 4];
    while (p < e) {
        int pn = p + 2;
        int sC = (pn + 2 < e) ? g_col[pn + 2] : -1;
        F4U vB;
        vB.f4 = make_float4(0.f, 0.f, 0.f, 0.f);
        if (sB >= 0)
            vB.f4 = *(const float4*)&g_h[(size_t)sB * 64 + q * 4];
        fadd2(acc0, vA.u[0]);
        fadd2(acc1, vA.u[1]);
        vA = vB;
        sB = sC;
        p = pn;
    }

    // combine the two half-warp accumulators (64-bit shfl)
    unsigned long long o0 = __shfl_down_sync(0xffffffffu, acc0, 16);
    unsigned long long o1 = __shfl_down_sync(0xffffffffu, acc1, 16);
    fadd2(acc0, o0);
    fadd2(acc1, o1);

    if (half == 0) {
        F4U u;
        u.u[0] = acc0;
        u.u[1] = acc1;
        float4 bb = *(const float4*)&b[q * 4];
        float4 r;
        r.x = fmaxf(u.f4.x * di + bb.x, 0.f);
        r.y = fmaxf(u.f4.y * di + bb.y, 0.f);
        r.z = fmaxf(u.f4.z * di + bb.z, 0.f);
        r.w = fmaxf(u.f4.w * di + bb.w, 0.f);
        *(float4*)&g_tmp[(size_t)warp * 64 + q * 4] = r;
    }
}

// ---------------- pooling: exploit sorted batch, flush per graph-run ---------
__global__ void pool_kernel(const void* __restrict__ batch, int n) {
    int warp = (blockIdx.x * blockDim.x + threadIdx.x) >> 5;
    int lane = threadIdx.x & 31;
    int base = warp * 64;
    if (base >= n) return;
    int end = min(base + 64, n);
    int cg = load_idx(batch, base);
    float2 acc = make_float2(0.f, 0.f);
    for (int i = base; i < end; i++) {
        int g = load_idx(batch, i);
        if (g != cg) {
            atomicAdd(&g_pooled[cg * 64 + lane * 2 + 0], acc.x);
            atomicAdd(&g_pooled[cg * 64 + lane * 2 + 1], acc.y);
            acc = make_float2(0.f, 0.f);
            cg = g;
        }
        float2 v = *(const float2*)&g_tmp[(size_t)i * 64 + lane * 2];
        acc.x += v.x;
        acc.y += v.y;
    }
    atomicAdd(&g_pooled[cg * 64 + lane * 2 + 0], acc.x);
    atomicAdd(&g_pooled[cg * 64 + lane * 2 + 1], acc.y);
}

// ---------------- final: counts via binary search + mean + linear head -------
__global__ void final_kernel(const void* __restrict__ batch,
                             const float* __restrict__ lin_w,
                             const float* __restrict__ lin_b,
                             float* __restrict__ out, int n, int g) {
    int i = blockIdx.x * blockDim.x + threadIdx.x;
    if (i >= g) return;
    // count of graph i in sorted batch: upper_bound(i) - lower_bound(i)
    int lo = 0, hi = n;
    while (lo < hi) {                       // lower_bound(i)
        int mid = (lo + hi) >> 1;
        if (load_idx(batch, mid) < i) lo = mid + 1; else hi = mid;
    }
    int lb = lo;
    hi = n;
    while (lo < hi) {                       // upper_bound(i)
        int mid = (lo + hi) >> 1;
        if (load_idx(batch, mid) <= i) lo = mid + 1; else hi = mid;
    }
    float cnt = fmaxf((float)(lo - lb), 1.0f);
    float inv = 1.0f / cnt;
    float a0 = lin_b[0];
    float a1 = lin_b[1];
#pragma unroll
    for (int d = 0; d < 64; d++) {
        float p = g_pooled[i * 64 + d] * inv;
        a0 += p * lin_w[d * 2 + 0];
        a1 += p * lin_w[d * 2 + 1];
    }
    out[i * 2 + 0] = a0;
    out[i * 2 + 1] = a1;
}

// ---------------- launch ------------------------------------------------------
extern "C" void kernel_launch(void* const* d_in, const int* in_sizes, int n_in,
                              void* d_out, int out_size) {
    const float* x     = (const float*)d_in[0];
    const void*  ei    = d_in[1];
    const void*  batch = d_in[2];
    const float* W0    = (const float*)d_in[3];
    const float* b0    = (const float*)d_in[4];
    const float* W1    = (const float*)d_in[5];
    const float* b1    = (const float*)d_in[6];
    const float* W2    = (const float*)d_in[7];
    const float* b2    = (const float*)d_in[8];
    const float* lin_w = (const float*)d_in[9];
    const float* lin_b = (const float*)d_in[10];

    int n = in_sizes[0] / DIM;       // 100000
    int e = in_sizes[1] / 2;         // 1200000
    int nc = in_sizes[10];           // 2
    int g = out_size / nc;           // 128

    int nb = (n + SCAN_B - 1) / SCAN_B;   // 98 scan blocks
    int gemm_blocks = (n + 63) / 64;
    long long agg_threads = (long long)n * 32;
    int agg_blocks = (int)((agg_threads + 255) / 256);

    detect_zero_kernel<<<200, 512>>>((const int*)ei, n, g);        // 0
    degree_kernel<<<(e + 511) / 512, 512>>>(ei, e);                // 1
    scan1_kernel<<<nb, SCAN_B>>>(n);                               // 2
    scan23_kernel<<<nb, SCAN_B>>>(n);                              // 3 <- ncu
    gemm64_kernel<<<gemm_blocks, 256>>>(x, W0, n);                 // 4
    fill_kernel<<<(e + 511) / 512, 512>>>(ei, e);                  // 5
    aggregate_kernel<<<agg_blocks, 256>>>(b0, n);                  // 6
    gemm64_kernel<<<gemm_blocks, 256>>>(nullptr, W1, n);           // 7
    aggregate_kernel<<<agg_blocks, 256>>>(b1, n);                  // 8
    gemm64_kernel<<<gemm_blocks, 256>>>(nullptr, W2, n);           // 9
    aggregate_kernel<<<agg_blocks, 256>>>(b2, n);                  // 10
    pool_kernel<<<((n + 63) / 64 * 32 + 255) / 256, 256>>>(batch, n); // 11
    final_kernel<<<1, 128>>>(batch, lin_w, lin_b, (float*)d_out, n, g); // 12
}

// round 9
// speedup vs baseline: 1.2405x; 1.0694x over previous
#include <cuda_runtime.h>
#include <cuda_bf16.h>

// Problem constants (fixed by the dataset; arrays sized to them)
#define MAXN 100000
#define MAXE 1200000
#define DIM  64
#define MAXG 128
#define SCAN_B 1024   // elements per scan block

// ---------------- scratch (static device globals; no allocation) -------------
__device__ int   g_indeg[MAXN];
__device__ int   g_fill[MAXN];        // CSR cursor (init = rowptr)
__device__ int   g_rowptr[MAXN + 1];
__device__ float g_dinv[MAXN];
__device__ int   g_col[MAXE];
__device__ float g_tmp[(size_t)MAXN * DIM];   // agg output (layer features, f32)
__device__ __align__(16) __nv_bfloat16 g_h[(size_t)MAXN * DIM]; // gather operand
__device__ float g_pooled[MAXG * DIM];
__device__ int   g_bsum[1024];        // per-block degree sums
__device__ int   g_idx64;             // 1 if indices are int64, 0 if int32

// Flag-dispatched index load (int32[] or int64[]; values < 2^31).
__device__ __forceinline__ int load_idx(const void* p, long long i) {
    if (g_idx64) return (int)((const long long*)p)[i];
    return ((const int*)p)[i];
}

// ---------------- packed f32x2 helpers (Blackwell) ---------------------------
__device__ __forceinline__ unsigned long long pack2(float x, float y) {
    unsigned long long r;
    asm("mov.b64 %0,{%1,%2};" : "=l"(r) : "f"(x), "f"(y));
    return r;
}
__device__ __forceinline__ void fma2(unsigned long long& d,
                                     unsigned long long a,
                                     unsigned long long b) {
    asm("fma.rn.f32x2 %0,%1,%2,%0;" : "+l"(d) : "l"(a), "l"(b));
}
__device__ __forceinline__ void fadd2(unsigned long long& d,
                                      unsigned long long a) {
    asm("add.rn.f32x2 %0,%0,%1;" : "+l"(d) : "l"(a));
}
// accumulate a bf16x2 word into a packed f32x2 accumulator (ALU-pipe unpack)
__device__ __forceinline__ void addbf2(unsigned long long& acc, unsigned int w) {
    unsigned int lo = w << 16;
    unsigned int hi = w & 0xffff0000u;
    unsigned long long p;
    asm("mov.b64 %0,{%1,%2};" : "=l"(p) : "r"(lo), "r"(hi));
    fadd2(acc, p);
}
union F4U { float4 f4; unsigned long long u[2]; float f[4]; };

// ---------------- detect dtype + zero scratch (one kernel) -------------------
__global__ void detect_zero_kernel(const int* __restrict__ ei32, int n, int g) {
    if (blockIdx.x == 0 && threadIdx.x == 0) {
        // int64 edge_index => every odd int32 word (high half) of the first
        // 32 values is 0. int32 => odd words are random node ids.
        int all_zero = 1;
        for (int k = 0; k < 32; k++)
            if (ei32[2 * k + 1] != 0) all_zero = 0;
        g_idx64 = all_zero;
    }
    int stride = gridDim.x * blockDim.x;
    int t = blockIdx.x * blockDim.x + threadIdx.x;
    for (int i = t; i < n; i += stride) g_indeg[i] = 0;
    for (int i = t; i < g * DIM; i += stride) g_pooled[i] = 0.0f;
}

// ---------------- degree histogram (at destination) --------------------------
__global__ void degree_kernel(const void* __restrict__ ei, int e) {
    int stride = gridDim.x * blockDim.x;
    for (int i = blockIdx.x * blockDim.x + threadIdx.x; i < e; i += stride)
        atomicAdd(&g_indeg[load_idx(ei, (long long)e + i)], 1);
}

// ---------------- scan phase 1: per-block degree sums + dinv -----------------
__global__ void scan1_kernel(int n) {
    __shared__ int wsum[32];
    int b = blockIdx.x, t = threadIdx.x;
    int i = b * SCAN_B + t;
    int lane = t & 31, wi = t >> 5;
    int v = 0;
    if (i < n) {
        v = g_indeg[i];
        g_dinv[i] = rsqrtf((float)v + 1.0f);   // dinv ready before gemm0
    }
    int s = v;
#pragma unroll
    for (int off = 16; off > 0; off >>= 1)
        s += __shfl_down_sync(0xffffffffu, s, off);
    if (lane == 0) wsum[wi] = s;
    __syncthreads();
    if (wi == 0) {
        int z = wsum[lane];
#pragma unroll
        for (int off = 16; off > 0; off >>= 1)
            z += __shfl_down_sync(0xffffffffu, z, off);
        if (lane == 0) g_bsum[b] = z;
    }
}

// ---------------- scan phase 2+3: rowptr + fill cursor -----------------------
__global__ void scan23_kernel(int n) {
    __shared__ int s_boff;
    __shared__ int wtot[32];
    int b = blockIdx.x, t = threadIdx.x;
    int lane = t & 31, wi = t >> 5;
    int i = b * SCAN_B + t;

    // block offset: warp 0 sums bsum[0..b-1] (<= 97 values)
    if (wi == 0) {
        int sum = 0;
        for (int j = lane; j < b; j += 32) sum += g_bsum[j];
#pragma unroll
        for (int off = 16; off > 0; off >>= 1)
            sum += __shfl_down_sync(0xffffffffu, sum, off);
        if (lane == 0) s_boff = sum;
    }

    int v = (i < n) ? g_indeg[i] : 0;
    int x = v;
#pragma unroll
    for (int off = 1; off < 32; off <<= 1) {     // inclusive warp scan
        int y = __shfl_up_sync(0xffffffffu, x, off);
        if (lane >= off) x += y;
    }
    if (lane == 31) wtot[wi] = x;
    __syncthreads();
    if (wi == 0) {
        int y = wtot[lane];
        int z = y;
#pragma unroll
        for (int off = 1; off < 32; off <<= 1) {
            int u = __shfl_up_sync(0xffffffffu, z, off);
            if (lane >= off) z += u;
        }
        wtot[lane] = z - y;                      // exclusive warp offsets
    }
    __syncthreads();

    if (i < n) {
        int excl = x - v + wtot[wi] + s_boff;
        g_rowptr[i] = excl;
        g_fill[i]   = excl;                      // cursor starts at rowptr
        if (i == n - 1) g_rowptr[n] = excl + v;
    }
}

// ---------------- CSR fill: col (src) only -----------------------------------
__global__ void fill_kernel(const void* __restrict__ ei, int e) {
    int stride = gridDim.x * blockDim.x;
    for (int i = blockIdx.x * blockDim.x + threadIdx.x; i < e; i += stride) {
        int s = load_idx(ei, i);                 // src row
        int d = load_idx(ei, (long long)e + i);  // dst row
        int pos = atomicAdd(&g_fill[d], 1);
        g_col[pos] = s;
    }
}

// ---------------- dense GEMM: g_h[n,64] = bf16((in @ W) * dinv) --------------
// in == nullptr means "read from g_tmp". Accumulate f32, round once to bf16.
__global__ __launch_bounds__(256) void gemm64_kernel(
    const float* __restrict__ in, const float* __restrict__ W, int n) {
    __shared__ float sX[64][68];
    __shared__ float sW[64][68];
    const float* src = (in == nullptr) ? g_tmp : in;
    int t = threadIdx.x;
    int block0 = blockIdx.x * 64;

    for (int i = t; i < 64 * 16; i += 256) {
        int r = i >> 4;
        int c4 = (i & 15) << 2;
        *(float4*)&sW[r][c4] = *(const float4*)&W[r * 64 + c4];
        int node = block0 + r;
        float4 x4 = make_float4(0.f, 0.f, 0.f, 0.f);
        if (node < n)
            x4 = *(const float4*)&src[(size_t)node * 64 + c4];
        *(float4*)&sX[r][c4] = x4;
    }
    __syncthreads();

    int tc = (t & 15) << 2;   // output col base
    int tr = (t >> 4) << 2;   // node base within tile
    unsigned long long acc[4][2] = {};
#pragma unroll
    for (int k4 = 0; k4 < 64; k4 += 4) {
        float4 a[4];
#pragma unroll
        for (int i = 0; i < 4; i++)
            a[i] = *(const float4*)&sX[tr + i][k4];   // LDS.128 along k
#pragma unroll
        for (int j = 0; j < 4; j++) {
            const unsigned long long* bp =
                (const unsigned long long*)&sW[k4 + j][tc];
            unsigned long long b01 = bp[0];
            unsigned long long b23 = bp[1];
            float aj0 = (&a[0].x)[j];
            float aj1 = (&a[1].x)[j];
            float aj2 = (&a[2].x)[j];
            float aj3 = (&a[3].x)[j];
            unsigned long long p0 = pack2(aj0, aj0);
            unsigned long long p1 = pack2(aj1, aj1);
            unsigned long long p2 = pack2(aj2, aj2);
            unsigned long long p3 = pack2(aj3, aj3);
            fma2(acc[0][0], p0, b01); fma2(acc[0][1], p0, b23);
            fma2(acc[1][0], p1, b01); fma2(acc[1][1], p1, b23);
            fma2(acc[2][0], p2, b01); fma2(acc[2][1], p2, b23);
            fma2(acc[3][0], p3, b01); fma2(acc[3][1], p3, b23);
        }
    }
#pragma unroll
    for (int i = 0; i < 4; i++) {
        int node = block0 + tr + i;
        if (node < n) {
            float sc = g_dinv[node];
            F4U u;
            u.u[0] = acc[i][0];
            u.u[1] = acc[i][1];
            __nv_bfloat162 c0 = __float22bfloat162_rn(
                make_float2(u.f4.x * sc, u.f4.y * sc));
            __nv_bfloat162 c1 = __float22bfloat162_rn(
                make_float2(u.f4.z * sc, u.f4.w * sc));
            uint2 st;
            st.x = *(unsigned int*)&c0;
            st.y = *(unsigned int*)&c1;
            *(uint2*)&g_h[(size_t)node * 64 + tc] = st;
        }
    }
}

// ---------------- aggregation: warp/node, quarter-warp/edge, bf16 gather -----
// g_tmp[i] = relu( dinv[i] * ( sum_e g_h[col[e]] + g_h[i] ) + b )
__global__ __launch_bounds__(256) void aggregate_kernel(
    const float* __restrict__ b, int n) {
    int warp = (blockIdx.x * blockDim.x + threadIdx.x) >> 5;
    if (warp >= n) return;
    int lane = threadIdx.x & 31;
    int es = lane >> 3;       // edge slot 0..3
    int q = lane & 7;         // 16B feature group (8 bf16 = features 8q..8q+7)
    int s = g_rowptr[warp];
    int e = g_rowptr[warp + 1];
    float di = g_dinv[warp];

    unsigned long long a0 = 0, a1 = 0, a2 = 0, a3 = 0;
    if (es == 0) {            // self term once
        uint4 sv = ((const uint4*)&g_h[(size_t)warp * 64])[q];
        addbf2(a0, sv.x); addbf2(a1, sv.y);
        addbf2(a2, sv.z); addbf2(a3, sv.w);
    }

    // four edges per warp-iteration, depth-2 prefetch (8 gathers in flight)
    int p = s + es;
    int sA = (p < e) ? g_col[p] : -1;
    int sB = (p + 4 < e) ? g_col[p + 4] : -1;
    uint4 vA = make_uint4(0u, 0u, 0u, 0u);
    if (sA >= 0) vA = ((const uint4*)&g_h[(size_t)sA * 64])[q];
    while (p < e) {
        int pn = p + 4;
        int sC = (pn + 4 < e) ? g_col[pn + 4] : -1;
        uint4 vB = make_uint4(0u, 0u, 0u, 0u);
        if (sB >= 0) vB = ((const uint4*)&g_h[(size_t)sB * 64])[q];
        addbf2(a0, vA.x); addbf2(a1, vA.y);
        addbf2(a2, vA.z); addbf2(a3, vA.w);
        vA = vB; sB = sC; p = pn;
    }

    // combine the four quarter-warp accumulators (packed shfl tree)
    fadd2(a0, __shfl_down_sync(0xffffffffu, a0, 16));
    fadd2(a1, __shfl_down_sync(0xffffffffu, a1, 16));
    fadd2(a2, __shfl_down_sync(0xffffffffu, a2, 16));
    fadd2(a3, __shfl_down_sync(0xffffffffu, a3, 16));
    fadd2(a0, __shfl_down_sync(0xffffffffu, a0, 8));
    fadd2(a1, __shfl_down_sync(0xffffffffu, a1, 8));
    fadd2(a2, __shfl_down_sync(0xffffffffu, a2, 8));
    fadd2(a3, __shfl_down_sync(0xffffffffu, a3, 8));

    if (lane < 8) {
        F4U lo4, hi4;
        lo4.u[0] = a0; lo4.u[1] = a1;     // features 8q..8q+3
        hi4.u[0] = a2; hi4.u[1] = a3;     // features 8q+4..8q+7
        float4 bb0 = *(const float4*)&b[q * 8 + 0];
        float4 bb1 = *(const float4*)&b[q * 8 + 4];
        float4 r0, r1;
        r0.x = fmaxf(lo4.f4.x * di + bb0.x, 0.f);
        r0.y = fmaxf(lo4.f4.y * di + bb0.y, 0.f);
        r0.z = fmaxf(lo4.f4.z * di + bb0.z, 0.f);
        r0.w = fmaxf(lo4.f4.w * di + bb0.w, 0.f);
        r1.x = fmaxf(hi4.f4.x * di + bb1.x, 0.f);
        r1.y = fmaxf(hi4.f4.y * di + bb1.y, 0.f);
        r1.z = fmaxf(hi4.f4.z * di + bb1.z, 0.f);
        r1.w = fmaxf(hi4.f4.w * di + bb1.w, 0.f);
        *(float4*)&g_tmp[(size_t)warp * 64 + q * 8 + 0] = r0;
        *(float4*)&g_tmp[(size_t)warp * 64 + q * 8 + 4] = r1;
    }
}

// ---------------- pooling: exploit sorted batch, flush per graph-run ---------
__global__ void pool_kernel(const void* __restrict__ batch, int n) {
    int warp = (blockIdx.x * blockDim.x + threadIdx.x) >> 5;
    int lane = threadIdx.x & 31;
    int base = warp * 64;
    if (base >= n) return;
    int end = min(base + 64, n);
    int cg = load_idx(batch, base);
    float2 acc = make_float2(0.f, 0.f);
    for (int i = base; i < end; i++) {
        int g = load_idx(batch, i);
        if (g != cg) {
            atomicAdd(&g_pooled[cg * 64 + lane * 2 + 0], acc.x);
            atomicAdd(&g_pooled[cg * 64 + lane * 2 + 1], acc.y);
            acc = make_float2(0.f, 0.f);
            cg = g;
        }
        float2 v = *(const float2*)&g_tmp[(size_t)i * 64 + lane * 2];
        acc.x += v.x;
        acc.y += v.y;
    }
    atomicAdd(&g_pooled[cg * 64 + lane * 2 + 0], acc.x);
    atomicAdd(&g_pooled[cg * 64 + lane * 2 + 1], acc.y);
}

// ---------------- final: counts via binary search + mean + linear head -------
__global__ void final_kernel(const void* __restrict__ batch,
                             const float* __restrict__ lin_w,
                             const float* __restrict__ lin_b,
                             float* __restrict__ out, int n, int g) {
    int i = blockIdx.x * blockDim.x + threadIdx.x;
    if (i >= g) return;
    int lo = 0, hi = n;
    while (lo < hi) {                       // lower_bound(i)
        int mid = (lo + hi) >> 1;
        if (load_idx(batch, mid) < i) lo = mid + 1; else hi = mid;
    }
    int lb = lo;
    hi = n;
    while (lo < hi) {                       // upper_bound(i)
        int mid = (lo + hi) >> 1;
        if (load_idx(batch, mid) <= i) lo = mid + 1; else hi = mid;
    }
    float cnt = fmaxf((float)(lo - lb), 1.0f);
    float inv = 1.0f / cnt;
    float a0 = lin_b[0];
    float a1 = lin_b[1];
#pragma unroll
    for (int d = 0; d < 64; d++) {
        float p = g_pooled[i * 64 + d] * inv;
        a0 += p * lin_w[d * 2 + 0];
        a1 += p * lin_w[d * 2 + 1];
    }
    out[i * 2 + 0] = a0;
    out[i * 2 + 1] = a1;
}

// ---------------- launch ------------------------------------------------------
extern "C" void kernel_launch(void* const* d_in, const int* in_sizes, int n_in,
                              void* d_out, int out_size) {
    const float* x     = (const float*)d_in[0];
    const void*  ei    = d_in[1];
    const void*  batch = d_in[2];
    const float* W0    = (const float*)d_in[3];
    const float* b0    = (const float*)d_in[4];
    const float* W1    = (const float*)d_in[5];
    const float* b1    = (const float*)d_in[6];
    const float* W2    = (const float*)d_in[7];
    const float* b2    = (const float*)d_in[8];
    const float* lin_w = (const float*)d_in[9];
    const float* lin_b = (const float*)d_in[10];

    int n = in_sizes[0] / DIM;       // 100000
    int e = in_sizes[1] / 2;         // 1200000
    int nc = in_sizes[10];           // 2
    int g = out_size / nc;           // 128

    int nb = (n + SCAN_B - 1) / SCAN_B;   // 98 scan blocks
    int gemm_blocks = (n + 63) / 64;
    long long agg_threads = (long long)n * 32;
    int agg_blocks = (int)((agg_threads + 255) / 256);

    detect_zero_kernel<<<200, 512>>>((const int*)ei, n, g);        // 0
    degree_kernel<<<(e + 511) / 512, 512>>>(ei, e);                // 1
    scan1_kernel<<<nb, SCAN_B>>>(n);                               // 2 (+dinv)
    gemm64_kernel<<<gemm_blocks, 256>>>(x, W0, n);                 // 3 <- ncu
    scan23_kernel<<<nb, SCAN_B>>>(n);                              // 4
    fill_kernel<<<(e + 511) / 512, 512>>>(ei, e);                  // 5
    aggregate_kernel<<<agg_blocks, 256>>>(b0, n);                  // 6
    gemm64_kernel<<<gemm_blocks, 256>>>(nullptr, W1, n);           // 7
    aggregate_kernel<<<agg_blocks, 256>>>(b1, n);                  // 8
    gemm64_kernel<<<gemm_blocks, 256>>>(nullptr, W2, n);           // 9
    aggregate_kernel<<<agg_blocks, 256>>>(b2, n);                  // 10
    pool_kernel<<<((n + 63) / 64 * 32 + 255) / 256, 256>>>(batch, n); // 11
    final_kernel<<<1, 128>>>(batch, lin_w, lin_b, (float*)d_out, n, g); // 12
}

// round 11
// speedup vs baseline: 1.4561x; 1.1738x over previous
#include <cuda_runtime.h>
#include <cuda_bf16.h>

// Problem constants (fixed by the dataset; arrays sized to them)
#define MAXN 100000
#define MAXE 1200000
#define DIM  64
#define MAXG 128
#define SCAN_B 1024   // elements per scan block

// ---------------- scratch (static device globals; no allocation) -------------
__device__ int   g_indeg[MAXN];
__device__ int   g_fill[MAXN];        // CSR cursor (init = rowptr)
__device__ int   g_rowptr[MAXN + 1];
__device__ float g_dinv[MAXN];
__device__ int   g_col[MAXE];
__device__ __align__(16) __nv_bfloat16 g_tmp[(size_t)MAXN * DIM]; // activations
__device__ __align__(16) __nv_bfloat16 g_h[(size_t)MAXN * DIM];   // gather operand
__device__ float g_pooled[MAXG * DIM];
__device__ int   g_bsum[1024];        // per-block degree sums
__device__ int   g_idx64;             // 1 if indices are int64, 0 if int32

// Flag-dispatched index load (int32[] or int64[]; values < 2^31).
__device__ __forceinline__ int load_idx(const void* p, long long i) {
    if (g_idx64) return (int)((const long long*)p)[i];
    return ((const int*)p)[i];
}

// ---------------- packed helpers ---------------------------------------------
__device__ __forceinline__ void fadd2(unsigned long long& d,
                                      unsigned long long a) {
    asm("add.rn.f32x2 %0,%0,%1;" : "+l"(d) : "l"(a));
}
// accumulate a bf16x2 word into a packed f32x2 accumulator (ALU-pipe unpack)
__device__ __forceinline__ void addbf2(unsigned long long& acc, unsigned int w) {
    unsigned int lo = w << 16;
    unsigned int hi = w & 0xffff0000u;
    unsigned long long p;
    asm("mov.b64 %0,{%1,%2};" : "=l"(p) : "r"(lo), "r"(hi));
    fadd2(acc, p);
}
__device__ __forceinline__ unsigned int bf2(float x, float y) {
    __nv_bfloat162 h = __float22bfloat162_rn(make_float2(x, y));
    return *(unsigned int*)&h;
}
// split f32 -> (hi, lo) bf16 pair packed as two bf16x2 words per 2 inputs
__device__ __forceinline__ void bfsplit2(float x, float y,
                                         unsigned int& hi, unsigned int& lo) {
    __nv_bfloat16 hx = __float2bfloat16_rn(x);
    __nv_bfloat16 hy = __float2bfloat16_rn(y);
    __nv_bfloat16 lx = __float2bfloat16_rn(x - __bfloat162float(hx));
    __nv_bfloat16 ly = __float2bfloat16_rn(y - __bfloat162float(hy));
    __nv_bfloat162 h2 = __halves2bfloat162(hx, hy);
    __nv_bfloat162 l2 = __halves2bfloat162(lx, ly);
    hi = *(unsigned int*)&h2;
    lo = *(unsigned int*)&l2;
}
union F4U { float4 f4; unsigned long long u[2]; float f[4]; };

// ---------------- detect dtype + zero scratch (one kernel) -------------------
__global__ void detect_zero_kernel(const int* __restrict__ ei32, int n, int g) {
    if (blockIdx.x == 0 && threadIdx.x == 0) {
        int all_zero = 1;
        for (int k = 0; k < 32; k++)
            if (ei32[2 * k + 1] != 0) all_zero = 0;
        g_idx64 = all_zero;
    }
    int stride = gridDim.x * blockDim.x;
    int t = blockIdx.x * blockDim.x + threadIdx.x;
    for (int i = t; i < n; i += stride) g_indeg[i] = 0;
    for (int i = t; i < g * DIM; i += stride) g_pooled[i] = 0.0f;
}

// ---------------- degree histogram (at destination) --------------------------
__global__ void degree_kernel(const void* __restrict__ ei, int e) {
    int stride = gridDim.x * blockDim.x;
    for (int i = blockIdx.x * blockDim.x + threadIdx.x; i < e; i += stride)
        atomicAdd(&g_indeg[load_idx(ei, (long long)e + i)], 1);
}

// ---------------- scan phase 1: per-block degree sums + dinv -----------------
__global__ void scan1_kernel(int n) {
    __shared__ int wsum[32];
    int b = blockIdx.x, t = threadIdx.x;
    int i = b * SCAN_B + t;
    int lane = t & 31, wi = t >> 5;
    int v = 0;
    if (i < n) {
        v = g_indeg[i];
        g_dinv[i] = rsqrtf((float)v + 1.0f);   // dinv ready before gemm0
    }
    int s = v;
#pragma unroll
    for (int off = 16; off > 0; off >>= 1)
        s += __shfl_down_sync(0xffffffffu, s, off);
    if (lane == 0) wsum[wi] = s;
    __syncthreads();
    if (wi == 0) {
        int z = wsum[lane];
#pragma unroll
        for (int off = 16; off > 0; off >>= 1)
            z += __shfl_down_sync(0xffffffffu, z, off);
        if (lane == 0) g_bsum[b] = z;
    }
}

// ---------------- scan phase 2+3: rowptr + fill cursor -----------------------
__global__ void scan23_kernel(int n) {
    __shared__ int s_boff;
    __shared__ int wtot[32];
    int b = blockIdx.x, t = threadIdx.x;
    int lane = t & 31, wi = t >> 5;
    int i = b * SCAN_B + t;

    if (wi == 0) {
        int sum = 0;
        for (int j = lane; j < b; j += 32) sum += g_bsum[j];
#pragma unroll
        for (int off = 16; off > 0; off >>= 1)
            sum += __shfl_down_sync(0xffffffffu, sum, off);
        if (lane == 0) s_boff = sum;
    }

    int v = (i < n) ? g_indeg[i] : 0;
    int x = v;
#pragma unroll
    for (int off = 1; off < 32; off <<= 1) {
        int y = __shfl_up_sync(0xffffffffu, x, off);
        if (lane >= off) x += y;
    }
    if (lane == 31) wtot[wi] = x;
    __syncthreads();
    if (wi == 0) {
        int y = wtot[lane];
        int z = y;
#pragma unroll
        for (int off = 1; off < 32; off <<= 1) {
            int u = __shfl_up_sync(0xffffffffu, z, off);
            if (lane >= off) z += u;
        }
        wtot[lane] = z - y;
    }
    __syncthreads();

    if (i < n) {
        int excl = x - v + wtot[wi] + s_boff;
        g_rowptr[i] = excl;
        g_fill[i]   = excl;
        if (i == n - 1) g_rowptr[n] = excl + v;
    }
}

// ---------------- CSR fill: col (src) only -----------------------------------
__global__ void fill_kernel(const void* __restrict__ ei, int e) {
    int stride = gridDim.x * blockDim.x;
    for (int i = blockIdx.x * blockDim.x + threadIdx.x; i < e; i += stride) {
        int s = load_idx(ei, i);
        int d = load_idx(ei, (long long)e + i);
        int pos = atomicAdd(&g_fill[d], 1);
        g_col[pos] = s;
    }
}

// ---------------- tensor-core GEMM: g_h = bf16((in @ W) * dinv) --------------
// 128-node x 64-col tile, 8 warps; warp = 16 rows x 64 cols.
// W split into hi+lo bf16 (removes systematic W-rounding error); A bf16
// (per-node errors average in pooling). Two MMA chains, one f32 accumulator.
__global__ __launch_bounds__(256) void gemm64_kernel(
    const float* __restrict__ in, const float* __restrict__ W, int n) {
    __shared__ __nv_bfloat16 sA[128][72];    // stride 144B: conflict-free ldsm
    __shared__ __nv_bfloat16 sBh[64][72];    // W_hi
    __shared__ __nv_bfloat16 sBl[64][72];    // W_lo = bf16(W - W_hi)
    int t = threadIdx.x;
    int block0 = blockIdx.x * 128;

    // stage W: f32 -> (hi, lo) bf16
    for (int idx = t; idx < 64 * 8; idx += 256) {
        int r = idx >> 3, c8 = (idx & 7) << 3;
        float4 w0 = *(const float4*)&W[r * 64 + c8];
        float4 w1 = *(const float4*)&W[r * 64 + c8 + 4];
        uint4 hi, lo;
        bfsplit2(w0.x, w0.y, hi.x, lo.x);
        bfsplit2(w0.z, w0.w, hi.y, lo.y);
        bfsplit2(w1.x, w1.y, hi.z, lo.z);
        bfsplit2(w1.z, w1.w, hi.w, lo.w);
        *(uint4*)&sBh[r][c8] = hi;
        *(uint4*)&sBl[r][c8] = lo;
    }
    // stage A: 128 rows (1024 groups of 8)
    for (int idx = t; idx < 128 * 8; idx += 256) {
        int r = idx >> 3, c8 = (idx & 7) << 3;
        int node = block0 + r;
        uint4 st = make_uint4(0u, 0u, 0u, 0u);
        if (node < n) {
            if (in != nullptr) {
                float4 x0 = *(const float4*)&in[(size_t)node * 64 + c8];
                float4 x1 = *(const float4*)&in[(size_t)node * 64 + c8 + 4];
                st.x = bf2(x0.x, x0.y); st.y = bf2(x0.z, x0.w);
                st.z = bf2(x1.x, x1.y); st.w = bf2(x1.z, x1.w);
            } else {
                st = *(const uint4*)&g_tmp[(size_t)node * 64 + c8];
            }
        }
        *(uint4*)&sA[r][c8] = st;
    }
    __syncthreads();

    int w = t >> 5, l = t & 31;
    float acc[8][4] = {};
#pragma unroll
    for (int k0 = 0; k0 < 64; k0 += 16) {
        // A fragment: 16x16, rows w*16..+15
        unsigned int a0, a1, a2, a3;
        {
            int row = (w << 4) + ((l >> 3) & 1) * 8 + (l & 7);
            int col = k0 + (l >> 4) * 8;
            unsigned int ad =
                (unsigned int)__cvta_generic_to_shared(&sA[row][col]);
            asm volatile(
                "ldmatrix.sync.aligned.m8n8.x4.shared.b16 {%0,%1,%2,%3},[%4];"
                : "=r"(a0), "=r"(a1), "=r"(a2), "=r"(a3) : "r"(ad));
        }
        // B fragments (hi and lo): 4 groups of 16 cols (k16 x n16, transposed)
        unsigned int bh[4][4], bl[4][4];
        int krow = k0 + ((l >> 3) & 1) * 8 + (l & 7);
        int bcol = (l >> 4) * 8;
#pragma unroll
        for (int g2 = 0; g2 < 4; g2++) {
            unsigned int adh =
                (unsigned int)__cvta_generic_to_shared(&sBh[krow][g2 * 16 + bcol]);
            asm volatile(
                "ldmatrix.sync.aligned.m8n8.x4.trans.shared.b16 "
                "{%0,%1,%2,%3},[%4];"
                : "=r"(bh[g2][0]), "=r"(bh[g2][1]),
                  "=r"(bh[g2][2]), "=r"(bh[g2][3]) : "r"(adh));
            unsigned int adl =
                (unsigned int)__cvta_generic_to_shared(&sBl[krow][g2 * 16 + bcol]);
            asm volatile(
                "ldmatrix.sync.aligned.m8n8.x4.trans.shared.b16 "
                "{%0,%1,%2,%3},[%4];"
                : "=r"(bl[g2][0]), "=r"(bl[g2][1]),
                  "=r"(bl[g2][2]), "=r"(bl[g2][3]) : "r"(adl));
        }
#pragma unroll
        for (int j = 0; j < 8; j++) {
            unsigned int b0 = bh[j >> 1][(j & 1) * 2];
            unsigned int b1 = bh[j >> 1][(j & 1) * 2 + 1];
            asm volatile(
                "mma.sync.aligned.m16n8k16.row.col.f32.bf16.bf16.f32 "
                "{%0,%1,%2,%3},{%4,%5,%6,%7},{%8,%9},{%0,%1,%2,%3};"
                : "+f"(acc[j][0]), "+f"(acc[j][1]),
                  "+f"(acc[j][2]), "+f"(acc[j][3])
                : "r"(a0), "r"(a1), "r"(a2), "r"(a3), "r"(b0), "r"(b1));
            unsigned int c0 = bl[j >> 1][(j & 1) * 2];
            unsigned int c1 = bl[j >> 1][(j & 1) * 2 + 1];
            asm volatile(
                "mma.sync.aligned.m16n8k16.row.col.f32.bf16.bf16.f32 "
                "{%0,%1,%2,%3},{%4,%5,%6,%7},{%8,%9},{%0,%1,%2,%3};"
                : "+f"(acc[j][0]), "+f"(acc[j][1]),
                  "+f"(acc[j][2]), "+f"(acc[j][3])
                : "r"(a0), "r"(a1), "r"(a2), "r"(a3), "r"(c0), "r"(c1));
        }
    }

    // epilogue: scale by dinv, round to bf16, store
    int r0 = block0 + (w << 4) + (l >> 2);
    int r1 = r0 + 8;
    float d0 = (r0 < n) ? g_dinv[r0] : 0.f;
    float d1 = (r1 < n) ? g_dinv[r1] : 0.f;
#pragma unroll
    for (int j = 0; j < 8; j++) {
        int c = j * 8 + (l & 3) * 2;
        if (r0 < n)
            *(unsigned int*)&g_h[(size_t)r0 * 64 + c] =
                bf2(acc[j][0] * d0, acc[j][1] * d0);
        if (r1 < n)
            *(unsigned int*)&g_h[(size_t)r1 * 64 + c] =
                bf2(acc[j][2] * d1, acc[j][3] * d1);
    }
}

// ---------------- aggregation: warp/node, quarter-warp/edge, bf16 gather -----
// g_tmp[i] = bf16( relu( dinv[i] * ( sum_e g_h[col[e]] + g_h[i] ) + b ) )
__global__ __launch_bounds__(256) void aggregate_kernel(
    const float* __restrict__ b, int n) {
    int warp = (blockIdx.x * blockDim.x + threadIdx.x) >> 5;
    if (warp >= n) return;
    int lane = threadIdx.x & 31;
    int es = lane >> 3;       // edge slot 0..3
    int q = lane & 7;         // 16B feature group (8 bf16 = features 8q..8q+7)
    int s = g_rowptr[warp];
    int e = g_rowptr[warp + 1];
    float di = g_dinv[warp];

    unsigned long long a0 = 0, a1 = 0, a2 = 0, a3 = 0;
    if (es == 0) {            // self term once
        uint4 sv = ((const uint4*)&g_h[(size_t)warp * 64])[q];
        addbf2(a0, sv.x); addbf2(a1, sv.y);
        addbf2(a2, sv.z); addbf2(a3, sv.w);
    }

    // four edges per warp-iteration, depth-2 prefetch (8 gathers in flight)
    int p = s + es;
    int sA = (p < e) ? g_col[p] : -1;
    int sB = (p + 4 < e) ? g_col[p + 4] : -1;
    uint4 vA = make_uint4(0u, 0u, 0u, 0u);
    if (sA >= 0) vA = ((const uint4*)&g_h[(size_t)sA * 64])[q];
    while (p < e) {
        int pn = p + 4;
        int sC = (pn + 4 < e) ? g_col[pn + 4] : -1;
        uint4 vB = make_uint4(0u, 0u, 0u, 0u);
        if (sB >= 0) vB = ((const uint4*)&g_h[(size_t)sB * 64])[q];
        addbf2(a0, vA.x); addbf2(a1, vA.y);
        addbf2(a2, vA.z); addbf2(a3, vA.w);
        vA = vB; sB = sC; p = pn;
    }

    // combine the four quarter-warp accumulators (packed shfl tree)
    fadd2(a0, __shfl_down_sync(0xffffffffu, a0, 16));
    fadd2(a1, __shfl_down_sync(0xffffffffu, a1, 16));
    fadd2(a2, __shfl_down_sync(0xffffffffu, a2, 16));
    fadd2(a3, __shfl_down_sync(0xffffffffu, a3, 16));
    fadd2(a0, __shfl_down_sync(0xffffffffu, a0, 8));
    fadd2(a1, __shfl_down_sync(0xffffffffu, a1, 8));
    fadd2(a2, __shfl_down_sync(0xffffffffu, a2, 8));
    fadd2(a3, __shfl_down_sync(0xffffffffu, a3, 8));

    if (lane < 8) {
        F4U lo4, hi4;
        lo4.u[0] = a0; lo4.u[1] = a1;     // features 8q..8q+3
        hi4.u[0] = a2; hi4.u[1] = a3;     // features 8q+4..8q+7
        float4 bb0 = *(const float4*)&b[q * 8 + 0];
        float4 bb1 = *(const float4*)&b[q * 8 + 4];
        uint4 st;
        st.x = bf2(fmaxf(lo4.f4.x * di + bb0.x, 0.f),
                   fmaxf(lo4.f4.y * di + bb0.y, 0.f));
        st.y = bf2(fmaxf(lo4.f4.z * di + bb0.z, 0.f),
                   fmaxf(lo4.f4.w * di + bb0.w, 0.f));
        st.z = bf2(fmaxf(hi4.f4.x * di + bb1.x, 0.f),
                   fmaxf(hi4.f4.y * di + bb1.y, 0.f));
        st.w = bf2(fmaxf(hi4.f4.z * di + bb1.z, 0.f),
                   fmaxf(hi4.f4.w * di + bb1.w, 0.f));
        *(uint4*)&g_tmp[(size_t)warp * 64 + q * 8] = st;
    }
}

// ---------------- pooling: exploit sorted batch, flush per graph-run ---------
__global__ void pool_kernel(const void* __restrict__ batch, int n) {
    int warp = (blockIdx.x * blockDim.x + threadIdx.x) >> 5;
    int lane = threadIdx.x & 31;
    int base = warp * 64;
    if (base >= n) return;
    int end = min(base + 64, n);
    int cg = load_idx(batch, base);
    float2 acc = make_float2(0.f, 0.f);
    for (int i = base; i < end; i++) {
        int g = load_idx(batch, i);
        if (g != cg) {
            atomicAdd(&g_pooled[cg * 64 + lane * 2 + 0], acc.x);
            atomicAdd(&g_pooled[cg * 64 + lane * 2 + 1], acc.y);
            acc = make_float2(0.f, 0.f);
            cg = g;
        }
        unsigned int wv = *(const unsigned int*)&g_tmp[(size_t)i * 64 + lane * 2];
        float2 v = __bfloat1622float2(*(__nv_bfloat162*)&wv);
        acc.x += v.x;
        acc.y += v.y;
    }
    atomicAdd(&g_pooled[cg * 64 + lane * 2 + 0], acc.x);
    atomicAdd(&g_pooled[cg * 64 + lane * 2 + 1], acc.y);
}

// ---------------- final: counts via binary search + mean + linear head -------
__global__ void final_kernel(const void* __restrict__ batch,
                             const float* __restrict__ lin_w,
                             const float* __restrict__ lin_b,
                             float* __restrict__ out, int n, int g) {
    int i = blockIdx.x * blockDim.x + threadIdx.x;
    if (i >= g) return;
    int lo = 0, hi = n;
    while (lo < hi) {
        int mid = (lo + hi) >> 1;
        if (load_idx(batch, mid) < i) lo = mid + 1; else hi = mid;
    }
    int lb = lo;
    hi = n;
    while (lo < hi) {
        int mid = (lo + hi) >> 1;
        if (load_idx(batch, mid) <= i) lo = mid + 1; else hi = mid;
    }
    float cnt = fmaxf((float)(lo - lb), 1.0f);
    float inv = 1.0f / cnt;
    float a0 = lin_b[0];
    float a1 = lin_b[1];
#pragma unroll
    for (int d = 0; d < 64; d++) {
        float p = g_pooled[i * 64 + d] * inv;
        a0 += p * lin_w[d * 2 + 0];
        a1 += p * lin_w[d * 2 + 1];
    }
    out[i * 2 + 0] = a0;
    out[i * 2 + 1] = a1;
}

// ---------------- launch ------------------------------------------------------
extern "C" void kernel_launch(void* const* d_in, const int* in_sizes, int n_in,
                              void* d_out, int out_size) {
    const float* x     = (const float*)d_in[0];
    const void*  ei    = d_in[1];
    const void*  batch = d_in[2];
    const float* W0    = (const float*)d_in[3];
    const float* b0    = (const float*)d_in[4];
    const float* W1    = (const float*)d_in[5];
    const float* b1    = (const float*)d_in[6];
    const float* W2    = (const float*)d_in[7];
    const float* b2    = (const float*)d_in[8];
    const float* lin_w = (const float*)d_in[9];
    const float* lin_b = (const float*)d_in[10];

    int n = in_sizes[0] / DIM;       // 100000
    int e = in_sizes[1] / 2;         // 1200000
    int nc = in_sizes[10];           // 2
    int g = out_size / nc;           // 128

    int nb = (n + SCAN_B - 1) / SCAN_B;   // 98 scan blocks
    int gemm_blocks = (n + 127) / 128;
    long long agg_threads = (long long)n * 32;
    int agg_blocks = (int)((agg_threads + 255) / 256);

    detect_zero_kernel<<<200, 512>>>((const int*)ei, n, g);        // 0
    degree_kernel<<<(e + 511) / 512, 512>>>(ei, e);                // 1
    scan1_kernel<<<nb, SCAN_B>>>(n);                               // 2 (+dinv)
    gemm64_kernel<<<gemm_blocks, 256>>>(x, W0, n);                 // 3 <- ncu
    scan23_kernel<<<nb, SCAN_B>>>(n);                              // 4
    fill_kernel<<<(e + 511) / 512, 512>>>(ei, e);                  // 5
    aggregate_kernel<<<agg_blocks, 256>>>(b0, n);                  // 6
    gemm64_kernel<<<gemm_blocks, 256>>>(nullptr, W1, n);           // 7
    aggregate_kernel<<<agg_blocks, 256>>>(b1, n);                  // 8
    gemm64_kernel<<<gemm_blocks, 256>>>(nullptr, W2, n);           // 9
    aggregate_kernel<<<agg_blocks, 256>>>(b2, n);                  // 10
    pool_kernel<<<((n + 63) / 64 * 32 + 255) / 256, 256>>>(batch, n); // 11
    final_kernel<<<1, 128>>>(batch, lin_w, lin_b, (float*)d_out, n, g); // 12
}